// round 9
// baseline (speedup 1.0000x reference)
#include <cuda_runtime.h>
#include <cuda_fp16.h>

// Dims fixed by the reference: x is (B=8, T=2048, F=128) float32.
#define BB 8
#define TT 2048
#define FF 128
#define NN (BB * TT * FF)           // 2,097,152
#define SB (TT * FF)                // 262144
#define ST (FF)                     // 128

#define TAU_F (1.0f / 6.0f)
#define NFUSED 28                   // updates #2..#29 (update #1 is k_first)

#define TTILE 2                     // T-rows per block tile (grid = 1024)
#define NWARP 8
#define NTHREADS (NWARP * 32)       // 256
#define F4 (FF / 4)                 // 32 float4/half4 per row == one warp

// Ping-pong dual buffers in fp16 (math stays fp32). No runtime allocation.
__device__ __half g_pa0[NN], g_pa1[NN], g_pa2[NN];
__device__ __half g_pb0[NN], g_pb1[NN], g_pb2[NN];

__device__ __forceinline__ float4 ld4(const float* __restrict__ p, int idx) {
    return *reinterpret_cast<const float4*>(p + idx);
}
__device__ __forceinline__ void st4(float* __restrict__ p, int idx, float4 v) {
    *reinterpret_cast<float4*>(p + idx) = v;
}
__device__ __forceinline__ float4 u2tof4(uint2 u) {
    __half2 h0 = *reinterpret_cast<__half2*>(&u.x);
    __half2 h1 = *reinterpret_cast<__half2*>(&u.y);
    float2 f0 = __half22float2(h0);
    float2 f1 = __half22float2(h1);
    return make_float4(f0.x, f0.y, f1.x, f1.y);
}
__device__ __forceinline__ float4 ldh4(const __half* __restrict__ p, int idx) {
    return u2tof4(*reinterpret_cast<const uint2*>(p + idx));
}
__device__ __forceinline__ uint2 ldu2(const __half* __restrict__ p, int idx) {
    return *reinterpret_cast<const uint2*>(p + idx);
}
__device__ __forceinline__ void sth4(__half* __restrict__ p, int idx, float4 v) {
    __half2 h0 = __floats2half2_rn(v.x, v.y);
    __half2 h1 = __floats2half2_rn(v.z, v.w);
    uint2 u;
    u.x = *reinterpret_cast<unsigned*>(&h0);
    u.y = *reinterpret_cast<unsigned*>(&h1);
    *reinterpret_cast<uint2*>(p + idx) = u;
}
__device__ __forceinline__ float4 f4sub(float4 a, float4 b) {
    return make_float4(a.x - b.x, a.y - b.y, a.z - b.z, a.w - b.w);
}
__device__ __forceinline__ float4 f4add(float4 a, float4 b) {
    return make_float4(a.x + b.x, a.y + b.y, a.z + b.z, a.w + b.w);
}

// ---------------------------------------------------------------------------
// k_first: p = 0  =>  out = img, g = grad(img). Writes pA (fp16).
// ---------------------------------------------------------------------------
__global__ __launch_bounds__(NTHREADS)
void k_first(const float* __restrict__ img, const float* __restrict__ lam) {
    int tid = blockIdx.x * blockDim.x + threadIdx.x;   // float4 index
    if (tid >= NN / 4) return;
    int lane = tid & 31;                               // == f4
    int t = (tid >> 5) & (TT - 1);
    int b = tid >> 16;
    int idx = tid * 4;

    float4 o = ld4(img, idx);
    float4 gb = make_float4(0, 0, 0, 0), gt = make_float4(0, 0, 0, 0), gf;
    if (b < BB - 1) gb = f4sub(ld4(img, idx + SB), o);
    if (t < TT - 1) gt = f4sub(ld4(img, idx + ST), o);
    float nx = __shfl_down_sync(0xffffffffu, o.x, 1);
    gf.x = o.y - o.x; gf.y = o.z - o.y; gf.z = o.w - o.z;
    gf.w = (lane < 31) ? (nx - o.w) : 0.0f;            // f==127 boundary

    float tw = TAU_F / lam[0];
    float4 r0, r1, r2;
#define FIRST_UPD(c)                                                     \
    { float n = sqrtf(gb.c * gb.c + gt.c * gt.c + gf.c * gf.c);          \
      float inv = __fdividef(1.0f, n * tw + 1.0f);                       \
      r0.c = (-TAU_F * gb.c) * inv;                                      \
      r1.c = (-TAU_F * gt.c) * inv;                                      \
      r2.c = (-TAU_F * gf.c) * inv; }
    FIRST_UPD(x) FIRST_UPD(y) FIRST_UPD(z) FIRST_UPD(w)
#undef FIRST_UPD
    sth4(g_pa0, idx, r0);
    sth4(g_pa1, idx, r1);
    sth4(g_pa2, idx, r2);
}

// ---------------------------------------------------------------------------
// k_fused: one Chambolle step. Block tile = (all 8 b) x (TTILE t-rows) x (F).
// Phase A: out = img + div(p_in) into smem (fp32) for TTILE+1 t-rows; the raw
//          fp16 p vectors for the TTILE interior rows are stashed in smem so
//          Phase B re-reads are LDS hits, not LDG.
// Phase B: gradients from smem, update p_out (fp16). Ping-pong p buffers.
// Both loops fully unrolled (trip counts 3 / 2) to front-batch the loads.
// ---------------------------------------------------------------------------
template <bool A2B>
__global__ __launch_bounds__(NTHREADS)
void k_fused(const float* __restrict__ img, const float* __restrict__ lam) {
    const __half* __restrict__ q0 = A2B ? g_pa0 : g_pb0;
    const __half* __restrict__ q1 = A2B ? g_pa1 : g_pb1;
    const __half* __restrict__ q2 = A2B ? g_pa2 : g_pb2;
    __half* __restrict__ r0 = A2B ? g_pb0 : g_pa0;
    __half* __restrict__ r1 = A2B ? g_pb1 : g_pa1;
    __half* __restrict__ r2 = A2B ? g_pb2 : g_pa2;

    __shared__ float4 s_out[BB][TTILE + 1][F4];        // 12 KB
    __shared__ uint2 s_p[3][BB][TTILE][F4];            // 12 KB (fp16 raw)

    int warp = threadIdx.x >> 5;
    int lane = threadIdx.x & 31;                        // == f4
    int t0 = blockIdx.x * TTILE;
    float tw = TAU_F / lam[0];

    // Phase A: 8*(TTILE+1) = 24 rows over 8 warps (3 each). Guards row-uniform.
#pragma unroll
    for (int r = warp; r < BB * (TTILE + 1); r += NWARP) {
        int b = r / (TTILE + 1);
        int trow = r - b * (TTILE + 1);
        int t = t0 + trow;
        if (t < TT) {
            int idx = b * SB + t * ST + lane * 4;
            float4 d = ld4(img, idx);
            uint2 u0 = ldu2(q0, idx);
            uint2 u1 = ldu2(q1, idx);
            uint2 u2 = ldu2(q2, idx);
            float4 a0 = u2tof4(u0);
            float4 a1 = u2tof4(u1);
            float4 a2 = u2tof4(u2);
            d = f4sub(f4sub(f4sub(d, a0), a1), a2);
            if (b > 0) d = f4add(d, ldh4(q0, idx - SB));
            if (t > 0) d = f4add(d, ldh4(q1, idx - ST));
            // + p2[f-1]: within-vector for y,z,w; lane-1's .w for x (0 at f==0)
            float prevw = __shfl_up_sync(0xffffffffu, a2.w, 1);
            if (lane > 0) d.x += prevw;
            d.y += a2.x; d.z += a2.y; d.w += a2.z;
            s_out[b][trow][lane] = d;
            if (trow < TTILE) {                         // stash for Phase B
                s_p[0][b][trow][lane] = u0;
                s_p[1][b][trow][lane] = u1;
                s_p[2][b][trow][lane] = u2;
            }
        }
    }
    __syncthreads();

    // Phase B: 8*TTILE = 16 rows over 8 warps (2 each).
#pragma unroll
    for (int r = warp; r < BB * TTILE; r += NWARP) {
        int b = r >> 1;                                 // r / TTILE
        int trow = r & (TTILE - 1);
        int t = t0 + trow;
        int idx = b * SB + t * ST + lane * 4;

        float4 o = s_out[b][trow][lane];
        float4 gb = make_float4(0, 0, 0, 0), gt = make_float4(0, 0, 0, 0), gf;
        if (b < BB - 1) gb = f4sub(s_out[b + 1][trow][lane], o);
        if (t < TT - 1) gt = f4sub(s_out[b][trow + 1][lane], o);
        float nx = __shfl_down_sync(0xffffffffu, o.x, 1);
        gf.x = o.y - o.x; gf.y = o.z - o.y; gf.z = o.w - o.z;
        gf.w = (lane < 31) ? (nx - o.w) : 0.0f;

        float4 a0 = u2tof4(s_p[0][b][trow][lane]);
        float4 a1 = u2tof4(s_p[1][b][trow][lane]);
        float4 a2 = u2tof4(s_p[2][b][trow][lane]);
        float4 o0, o1, o2;
#define UPD(c)                                                            \
        { float n = sqrtf(gb.c * gb.c + gt.c * gt.c + gf.c * gf.c);       \
          float inv = __fdividef(1.0f, n * tw + 1.0f);                    \
          o0.c = (a0.c - TAU_F * gb.c) * inv;                             \
          o1.c = (a1.c - TAU_F * gt.c) * inv;                             \
          o2.c = (a2.c - TAU_F * gf.c) * inv; }
        UPD(x) UPD(y) UPD(z) UPD(w)
#undef UPD
        sth4(r0, idx, o0);
        sth4(r1, idx, o1);
        sth4(r2, idx, o2);
    }
}

// ---------------------------------------------------------------------------
// k_final: out = img + div(pA) + bias[f]. One float4/thread.
// ---------------------------------------------------------------------------
__global__ __launch_bounds__(NTHREADS)
void k_final(const float* __restrict__ img, const float* __restrict__ bias,
             float* __restrict__ out) {
    int tid = blockIdx.x * blockDim.x + threadIdx.x;
    if (tid >= NN / 4) return;
    int lane = tid & 31;                               // == f4
    int t = (tid >> 5) & (TT - 1);
    int b = tid >> 16;
    int idx = tid * 4;

    float4 d = ld4(img, idx);
    float4 a0 = ldh4(g_pa0, idx);
    float4 a1 = ldh4(g_pa1, idx);
    float4 a2 = ldh4(g_pa2, idx);
    d = f4sub(f4sub(f4sub(d, a0), a1), a2);
    if (b > 0) d = f4add(d, ldh4(g_pa0, idx - SB));
    if (t > 0) d = f4add(d, ldh4(g_pa1, idx - ST));
    float prevw = __shfl_up_sync(0xffffffffu, a2.w, 1);
    if (lane > 0) d.x += prevw;
    d.y += a2.x; d.z += a2.y; d.w += a2.z;

    d = f4add(d, ld4(bias, lane * 4));
    st4(out, idx, d);
}

extern "C" void kernel_launch(void* const* d_in, const int* in_sizes, int n_in,
                              void* d_out, int out_size) {
    const float* x   = (const float*)d_in[0];   // (8, 2048, 128)
    const float* lam = (const float*)d_in[1];   // (1, 1)
    const float* b   = (const float*)d_in[2];   // (1, 1, 128)
    float* out = (float*)d_out;

    const int vblocks = (NN / 4 + NTHREADS - 1) / NTHREADS;   // 2048
    const int fblocks = TT / TTILE;                           // 1024

    k_first<<<vblocks, NTHREADS>>>(x, lam);

    for (int it = 0; it < NFUSED; ++it) {
        if ((it & 1) == 0)
            k_fused<true><<<fblocks, NTHREADS>>>(x, lam);   // A -> B
        else
            k_fused<false><<<fblocks, NTHREADS>>>(x, lam);  // B -> A
    }

    k_final<<<vblocks, NTHREADS>>>(x, b, out);
}